// round 16
// baseline (speedup 1.0000x reference)
#include <cuda_runtime.h>
#include <cuda_bf16.h>
#include <cstdint>

#define NB 32
#define E  512
#define IND 128
#define OUTD 64
#define NT 3
#define QD 128
#define CD 128   // 2*OUTD

// ---------------- scratch (__device__ globals: no allocs allowed) ----------
__device__ float g_wsrc[NT*NB*IND];
__device__ float g_wdst[NT*NB*IND];
__device__ float g_ssrc[NT*NB*E];
__device__ float g_sdst[NT*NB*E];
__device__ float g_rinvZ[NB*E];
// H transposed, bf16 hi/lo split: [n][d][e]
__device__ __nv_bfloat16 g_hmT_hi[(size_t)NB*OUTD*E];
__device__ __nv_bfloat16 g_hmT_lo[(size_t)NB*OUTD*E];
__device__ unsigned char g_adj8[(size_t)NB*E*E];    // packed adj (values 0..3)

__device__ __forceinline__ uint32_t smem_u32(const void* p) {
    uint32_t a;
    asm("{ .reg .u64 t; cvta.to.shared.u64 t, %1; cvt.u32.u64 %0, t; }"
        : "=r"(a) : "l"(p));
    return a;
}

#define LDSM4_T(R, addr) \
    asm volatile("ldmatrix.sync.aligned.m8n8.x4.trans.shared.b16 {%0,%1,%2,%3}, [%4];" \
        : "=r"((R)[0]), "=r"((R)[1]), "=r"((R)[2]), "=r"((R)[3]) : "r"(addr))
#define LDSM4(R, addr) \
    asm volatile("ldmatrix.sync.aligned.m8n8.x4.shared.b16 {%0,%1,%2,%3}, [%4];" \
        : "=r"((R)[0]), "=r"((R)[1]), "=r"((R)[2]), "=r"((R)[3]) : "r"(addr))
#define MMA16816(d, a, b0v, b1v) \
    asm volatile("mma.sync.aligned.m16n8k16.row.col.f32.bf16.bf16.f32 " \
        "{%0,%1,%2,%3}, {%4,%5,%6,%7}, {%8,%9}, {%0,%1,%2,%3};" \
        : "+f"((d)[0]), "+f"((d)[1]), "+f"((d)[2]), "+f"((d)[3]) \
        : "r"((a)[0]), "r"((a)[1]), "r"((a)[2]), "r"((a)[3]), "r"(b0v), "r"(b1v))

// ---------------------------------------------------------------------------
// Kernel 1: per (t,n) fold qg*a into 128-vectors w_src/w_dst
// ---------------------------------------------------------------------------
__global__ void prep_kernel(const float* __restrict__ qv,
                            const float* __restrict__ Wt,
                            const float* __restrict__ at,
                            const float* __restrict__ W1,
                            const float* __restrict__ W2) {
    int t = blockIdx.x / NB, n = blockIdx.x % NB;
    int c = threadIdx.x;                       // 0..127
    __shared__ float sq[QD], sg1[CD], su[CD];

    sq[c] = qv[n*QD + c];
    __syncthreads();

    const float* w1 = W1 + t*QD*CD;
    float acc = 0.f;
    #pragma unroll 8
    for (int q = 0; q < QD; q++) acc += sq[q] * w1[q*CD + c];
    sg1[c] = fmaxf(acc, 0.f);
    __syncthreads();

    const float* w2 = W2 + t*CD*CD;
    acc = 0.f;
    #pragma unroll 8
    for (int q = 0; q < CD; q++) acc += sg1[q] * w2[q*CD + c];
    float qg = 1.f / (1.f + expf(-acc));
    su[c] = qg * at[t*CD + c];
    __syncthreads();

    const float* W = Wt + (t*IND + c)*OUTD;
    float ws = 0.f, wd = 0.f;
    #pragma unroll 8
    for (int o = 0; o < OUTD; o++) {
        float w = W[o];
        ws += w * su[o];
        wd += w * su[OUTD + o];
    }
    g_wsrc[(t*NB + n)*IND + c] = ws;
    g_wdst[(t*NB + n)*IND + c] = wd;
}

// ---------------------------------------------------------------------------
// Kernel 2 (fused, TENSORIZED): h = (x @ W_type[2]) * mask via bf16 hi/lo
// 3-product mma.sync -> transposed bf16 hi/lo planes; ssd dots folded into
// the x->bf16 conversion pass. grid (NB, 8), 256 threads. (round-15 exact)
// ---------------------------------------------------------------------------
__global__ void __launch_bounds__(256)
hm_ssd_kernel(const float* __restrict__ x, const float* __restrict__ Wt,
              const float* __restrict__ mask) {
    extern __shared__ char sm2[];
    float* sw    = (float*)sm2;                // [6][128]
    float* smask = (float*)(sm2 + 3072);       // [64]
    char*  Xh    = sm2 + 3328;
    char*  Xl    = Xh + 17408;
    char*  Wh    = Xl + 17408;
    char*  Wl    = Wh + 17408;
    float* Hs    = (float*)Xh;                 // alias (post-MMA), pitch 65

    const int n = blockIdx.x, e0 = blockIdx.y * 64;
    const int tid = threadIdx.x;
    const int w = tid >> 5, lane = tid & 31;
    const int wm = w & 3, wn = w >> 2;         // warp tile: e=wm*16, d=wn*32
    const uint32_t sb = smem_u32(sm2);

    for (int k = tid; k < 6*IND; k += 256) {
        int v = k / IND, i = k % IND;
        int t = v % 3;
        sw[k] = (v < 3) ? g_wsrc[(t*NB+n)*IND + i] : g_wdst[(t*NB+n)*IND + i];
    }
    if (tid < 64) smask[tid] = mask[n*E + e0 + tid];

    // W_type[2] transpose + bf16 hi/lo convert: [k][d] -> Wh/Wl[d][k]
    for (int idx = tid; idx < IND*OUTD; idx += 256) {
        int k = idx >> 6, d = idx & 63;
        float v = Wt[2*IND*OUTD + k*OUTD + d];
        __nv_bfloat16 h = __float2bfloat16(v);
        *(__nv_bfloat16*)(Wh + d*272 + k*2) = h;
        *(__nv_bfloat16*)(Wl + d*272 + k*2) = __float2bfloat16(v - __bfloat162float(h));
    }

    // x convert (fp32 -> bf16 hi/lo planes) + ssd accumulate
    {
        int r = tid >> 2, q = tid & 3;         // 4 threads per e-row
        const float* xr = x + ((size_t)n*E + e0 + r)*IND;
        float a[6] = {0.f,0.f,0.f,0.f,0.f,0.f};
        #pragma unroll
        for (int u = 0; u < 8; u++) {
            int k = u*16 + q*4;
            float4 v = *(const float4*)(xr + k);
            #pragma unroll
            for (int j = 0; j < 6; j++) {
                const float* s = &sw[j*IND + k];
                a[j] += v.x*s[0] + v.y*s[1] + v.z*s[2] + v.w*s[3];
            }
            __nv_bfloat16 h0 = __float2bfloat16(v.x), h1 = __float2bfloat16(v.y);
            __nv_bfloat16 h2 = __float2bfloat16(v.z), h3 = __float2bfloat16(v.w);
            __nv_bfloat162 hp0 = __halves2bfloat162(h0, h1);
            __nv_bfloat162 hp1 = __halves2bfloat162(h2, h3);
            *(uint32_t*)(Xh + r*272 + k*2)     = *(uint32_t*)&hp0;
            *(uint32_t*)(Xh + r*272 + k*2 + 4) = *(uint32_t*)&hp1;
            __nv_bfloat162 lp0 = __halves2bfloat162(
                __float2bfloat16(v.x - __bfloat162float(h0)),
                __float2bfloat16(v.y - __bfloat162float(h1)));
            __nv_bfloat162 lp1 = __halves2bfloat162(
                __float2bfloat16(v.z - __bfloat162float(h2)),
                __float2bfloat16(v.w - __bfloat162float(h3)));
            *(uint32_t*)(Xl + r*272 + k*2)     = *(uint32_t*)&lp0;
            *(uint32_t*)(Xl + r*272 + k*2 + 4) = *(uint32_t*)&lp1;
        }
        #pragma unroll
        for (int off = 1; off <= 2; off <<= 1)
            #pragma unroll
            for (int u2 = 0; u2 < 6; u2++)
                a[u2] += __shfl_xor_sync(0xffffffffu, a[u2], off);
        if (q == 0) {
            int e = e0 + r;
            #pragma unroll
            for (int t = 0; t < 3; t++) {
                g_ssrc[(t*NB+n)*E + e] = a[t];
                g_sdst[(t*NB+n)*E + e] = a[t+3];
            }
        }
    }
    __syncthreads();

    // tensor-core h GEMM: A = x[e][k] (non-trans), B = W^T[d][k]
    float acc[2][2][4] = {};                   // [cp][n8][frag]
    const uint32_t aX = sb + 3328
        + (wm*16 + (lane & 7) + ((lane>>3)&1)*8)*272 + ((lane>>4)&1)*16;
    const uint32_t aW = sb + 3328 + 2*17408
        + ((uint32_t)wn*32 + ((lane>>4)&1)*8 + (lane & 7))*272 + ((lane>>3)&1)*16;
    #pragma unroll
    for (int kk = 0; kk < 8; kk++) {
        uint32_t a_h[4], a_l[4];
        LDSM4(a_h, aX + kk*32);
        LDSM4(a_l, aX + 17408 + kk*32);
        #pragma unroll
        for (int cp = 0; cp < 2; cp++) {
            uint32_t b_h[4], b_l[4];
            uint32_t bd = aW + cp*16*272 + kk*32;
            LDSM4(b_h, bd);
            LDSM4(b_l, bd + 17408);
            float* d0 = acc[cp][0];
            float* d1 = acc[cp][1];
            MMA16816(d0, a_h, b_h[0], b_h[1]);
            MMA16816(d0, a_h, b_l[0], b_l[1]);
            MMA16816(d0, a_l, b_h[0], b_h[1]);
            MMA16816(d1, a_h, b_h[2], b_h[3]);
            MMA16816(d1, a_h, b_l[2], b_l[3]);
            MMA16816(d1, a_l, b_h[2], b_h[3]);
        }
    }
    __syncthreads();                           // all X-plane reads done

    // write Hs[e][d] (fp32, mask applied); Hs aliases Xh
    {
        const int g = lane >> 2, t2 = (lane & 3)*2;
        #pragma unroll
        for (int cp = 0; cp < 2; cp++) {
            #pragma unroll
            for (int ct = 0; ct < 2; ct++) {
                int e1 = wm*16 + g;
                int d  = wn*32 + cp*16 + ct*8 + t2;
                float mk0 = smask[e1], mk1 = smask[e1 + 8];
                Hs[e1*65 + d]       = acc[cp][ct][0] * mk0;
                Hs[e1*65 + d + 1]   = acc[cp][ct][1] * mk0;
                Hs[(e1+8)*65 + d]     = acc[cp][ct][2] * mk1;
                Hs[(e1+8)*65 + d + 1] = acc[cp][ct][3] * mk1;
            }
        }
    }
    __syncthreads();

    // coalesced 16B writes of both planes: task = (d, e-group of 8)
    #pragma unroll
    for (int u = 0; u < 2; u++) {
        int task = tid + u*256;                // 0..511
        int d = task >> 3, g = task & 7;
        uint32_t hv[4], lv[4];
        #pragma unroll
        for (int p = 0; p < 4; p++) {
            float v0 = Hs[(g*8 + 2*p + 0)*65 + d];
            float v1 = Hs[(g*8 + 2*p + 1)*65 + d];
            __nv_bfloat16 h0 = __float2bfloat16(v0);
            __nv_bfloat16 h1 = __float2bfloat16(v1);
            __nv_bfloat162 hp = __halves2bfloat162(h0, h1);
            hv[p] = *(uint32_t*)&hp;
            __nv_bfloat162 lp = __halves2bfloat162(
                __float2bfloat16(v0 - __bfloat162float(h0)),
                __float2bfloat16(v1 - __bfloat162float(h1)));
            lv[p] = *(uint32_t*)&lp;
        }
        size_t base = ((size_t)(n*OUTD + d))*E + e0 + g*8;
        *(uint4*)(g_hmT_hi + base) = make_uint4(hv[0], hv[1], hv[2], hv[3]);
        *(uint4*)(g_hmT_lo + base) = make_uint4(lv[0], lv[1], lv[2], lv[3]);
    }
}

// ---------------------------------------------------------------------------
// Kernel 3: row softmax WITHOUT max-subtraction. 2 rows per warp -> ONE wave.
// grid NB*E/32 = 512, block 512. (round-15 exact)
// ---------------------------------------------------------------------------
__global__ void rowstats_kernel(const int* __restrict__ adj) {
    int base = blockIdx.x * 32;                // 32 rows per block, same n
    int n = base / E;
    __shared__ float sds[3][E];
    int tid = threadIdx.x;
    #pragma unroll
    for (int k = tid; k < 3*E; k += 512)
        sds[k >> 9][k & 511] = g_sdst[((k >> 9)*NB + n)*E + (k & 511)];
    __syncthreads();

    int warp = tid >> 5, lane = tid & 31;
    int row0 = base + warp*2, row1 = row0 + 1;
    int i0 = row0 & (E-1), i1 = row1 & (E-1);
    float sA0 = g_ssrc[(0*NB+n)*E + i0];
    float sA1 = g_ssrc[(1*NB+n)*E + i0];
    float sA2 = g_ssrc[(2*NB+n)*E + i0];
    float sB0 = g_ssrc[(0*NB+n)*E + i1];
    float sB1 = g_ssrc[(1*NB+n)*E + i1];
    float sB2 = g_ssrc[(2*NB+n)*E + i1];
    const int* ar0 = adj + (size_t)row0 * E;
    const int* ar1 = adj + (size_t)row1 * E;
    unsigned char* a80 = g_adj8 + (size_t)row0 * E;
    unsigned char* a81 = g_adj8 + (size_t)row1 * E;

    float sum0 = 0.f, sum1 = 0.f;
    #pragma unroll
    for (int k = 0; k < 16; k++) {
        int j = lane + 32*k;
        int v0 = ar0[j];
        int v1 = ar1[j];
        a80[j] = (unsigned char)v0;
        a81[j] = (unsigned char)v1;
        float s0 = -1e30f, s1 = -1e30f;
        if (v0 > 0) {
            float srr = (v0 == 1) ? sA0 : ((v0 == 2) ? sA1 : sA2);
            float t2 = srr + sds[v0-1][j];
            s0 = (t2 >= 0.f) ? t2 : 0.2f*t2;
        }
        if (v1 > 0) {
            float srr = (v1 == 1) ? sB0 : ((v1 == 2) ? sB1 : sB2);
            float t2 = srr + sds[v1-1][j];
            s1 = (t2 >= 0.f) ? t2 : 0.2f*t2;
        }
        sum0 += __expf(s0);
        sum1 += __expf(s1);
    }
    #pragma unroll
    for (int off = 16; off > 0; off >>= 1) {
        sum0 += __shfl_xor_sync(~0u, sum0, off);
        sum1 += __shfl_xor_sync(~0u, sum1, off);
    }
    if (lane == 0) {
        g_rinvZ[row0] = 1.f / sum0;
        g_rinvZ[row1] = 1.f / sum1;
    }
}

// ---------------------------------------------------------------------------
// Kernel 4: output GEMM on tensor cores (mma.sync bf16, hi/lo 3-product),
// SPLIT-K by 4, packed uint8 adj, coef = __expf(score)*invZ.
// CHANGE vs round 15: per-chunk stats live in registers (1 scalar/lane,
// shuffle-broadcast in gen) -> no stats smem, no staging pass, 2 barriers
// per chunk instead of 3; H staging overlaps gen. RED.ADD epilogue.
// grid (NB, E/128, 4), 256 thr, occ 4.
// ---------------------------------------------------------------------------
__global__ void __launch_bounds__(256, 4)
out_kernel(float* __restrict__ out) {
    extern __shared__ char sm[];
    const int CPL = 64*272;
    const int HPL = 64*144;
    char* Chi = sm;
    char* Hhi = sm + 2*CPL;
    char* Hlo = sm + 2*CPL + HPL;
    float* sds = (float*)(sm + 2*CPL + 2*HPL);  // [3][128]

    const int n = blockIdx.x, j0t = blockIdx.y * 128, kz = blockIdx.z;
    const int tid = threadIdx.x;
    const int w = tid >> 5, lane = tid & 31;
    const int wm = w & 3, wn = w >> 2;

    const uint32_t sbase = smem_u32(sm);

    for (int k = tid; k < 384; k += 256)
        sds[k] = g_sdst[((k>>7)*NB + n)*E + j0t + (k & 127)];

    float acc[2][4][4] = {};

    const uint32_t lr = lane & 7;
    const uint32_t aA0 = sbase
        + (((lane>>4)&1)*8 + lr)*272
        + (wm*32 + ((lane>>3)&1)*8)*2;
    const uint32_t aB0 = sbase + 2*CPL
        + ((uint32_t)wn*32 + ((lane>>4)&1)*8 + lr)*144
        + ((lane>>3)&1)*16;

    for (int ch = 0; ch < 2; ch++) {
        const int ic = kz*128 + ch*64;
        __syncthreads();                         // prev chunk's mma reads done
                                                 // (also covers sds on ch==0)

        // per-warp stats in registers: lane = (vv<<3)|s holds stat vv of
        // i-row (s*8 + w); vv: 0..2 = ssr[t], 3 = invZ
        float statv;
        {
            int s = lane & 7, vv = lane >> 3;
            int irow = ic + s*8 + w;
            statv = (vv < 3) ? g_ssrc[(vv*NB + n)*E + irow]
                             : g_rinvZ[n*E + irow];
        }

        // stage H^T hi/lo tiles (overlaps with gen below — same barrier)
        #pragma unroll
        for (int u = 0; u < 2; u++) {
            int k = tid + u*256;
            int d = k >> 3, i16 = k & 7;
            size_t src = ((size_t)(n*OUTD + d))*E + ic + i16*8;
            *(uint4*)(Hhi + d*144 + i16*16) = *(const uint4*)(g_hmT_hi + src);
            *(uint4*)(Hlo + d*144 + i16*16) = *(const uint4*)(g_hmT_lo + src);
        }

        // generate coef tile: warp w handles i rows {8s + w}
        const unsigned char* abase = g_adj8 + ((size_t)(n*E + ic))*E + j0t;
        #pragma unroll
        for (int s = 0; s < 8; s++) {
            int i = s*8 + w;
            uint32_t a4 = *(const uint32_t*)(abase + (size_t)i*E + lane*4);
            float s0 = __shfl_sync(~0u, statv, s);
            float s1 = __shfl_sync(~0u, statv, 8 + s);
            float s2 = __shfl_sync(~0u, statv, 16 + s);
            float z  = __shfl_sync(~0u, statv, 24 + s);
            float cf[4];
            #pragma unroll
            for (int q = 0; q < 4; q++) {
                int v = (int)((a4 >> (8*q)) & 0xFFu);
                float score = -1e30f;
                if (v > 0) {
                    float srr = (v == 1) ? s0 : ((v == 2) ? s1 : s2);
                    float t2 = srr + sds[(v-1)*128 + lane*4 + q];
                    score = (t2 >= 0.f) ? t2 : 0.2f*t2;
                }
                cf[q] = __expf(score) * z;
            }
            __nv_bfloat16 h0 = __float2bfloat16(cf[0]), h1 = __float2bfloat16(cf[1]);
            __nv_bfloat16 h2 = __float2bfloat16(cf[2]), h3 = __float2bfloat16(cf[3]);
            uint2 hv;
            ((__nv_bfloat162*)&hv)[0] = __halves2bfloat162(h0, h1);
            ((__nv_bfloat162*)&hv)[1] = __halves2bfloat162(h2, h3);
            uint2 lv;
            ((__nv_bfloat162*)&lv)[0] = __halves2bfloat162(
                __float2bfloat16(cf[0] - __bfloat162float(h0)),
                __float2bfloat16(cf[1] - __bfloat162float(h1)));
            ((__nv_bfloat162*)&lv)[1] = __halves2bfloat162(
                __float2bfloat16(cf[2] - __bfloat162float(h2)),
                __float2bfloat16(cf[3] - __bfloat162float(h3)));
            *(uint2*)(Chi + i*272 + lane*8)       = hv;
            *(uint2*)(Chi + CPL + i*272 + lane*8) = lv;
        }
        __syncthreads();                         // C + H visible to mma

        #pragma unroll
        for (int kk = 0; kk < 4; kk++) {
            uint32_t a_h[2][4], a_l[2][4];
            #pragma unroll
            for (int r = 0; r < 2; r++) {
                uint32_t ad = aA0 + kk*16*272 + r*32;
                LDSM4_T(a_h[r], ad);
                LDSM4_T(a_l[r], ad + CPL);
            }
            #pragma unroll
            for (int cp = 0; cp < 2; cp++) {
                uint32_t b_h[4], b_l[4];
                uint32_t bd = aB0 + cp*16*144 + kk*32;
                LDSM4(b_h, bd);
                LDSM4(b_l, bd + HPL);
                #pragma unroll
                for (int r = 0; r < 2; r++) {
                    float* d0 = acc[r][cp*2 + 0];
                    float* d1 = acc[r][cp*2 + 1];
                    MMA16816(d0, a_h[r], b_h[0], b_h[1]);
                    MMA16816(d0, a_h[r], b_l[0], b_l[1]);
                    MMA16816(d0, a_l[r], b_h[0], b_h[1]);
                    MMA16816(d1, a_h[r], b_h[2], b_h[3]);
                    MMA16816(d1, a_h[r], b_l[2], b_l[3]);
                    MMA16816(d1, a_l[r], b_h[2], b_h[3]);
                }
            }
        }
    }

    // epilogue: RED.ADD (no return) onto zeroed out
    const int g = lane >> 2, t2 = (lane & 3)*2;
    #pragma unroll
    for (int r = 0; r < 2; r++) {
        #pragma unroll
        for (int ct = 0; ct < 4; ct++) {
            int j = j0t + wm*32 + r*16 + g;
            int d = wn*32 + ct*8 + t2;
            float* p = out + ((size_t)(n*E + j))*OUTD + d;
            atomicAdd(p + 0, acc[r][ct][0]);
            atomicAdd(p + 1, acc[r][ct][1]);
            atomicAdd(p + 8*OUTD + 0, acc[r][ct][2]);
            atomicAdd(p + 8*OUTD + 1, acc[r][ct][3]);
        }
    }
}

// ---------------------------------------------------------------------------
extern "C" void kernel_launch(void* const* d_in, const int* in_sizes, int n_in,
                              void* d_out, int out_size) {
    const float* x    = (const float*)d_in[0];   // input_state (32,512,128)
    const int*   adj  = (const int*)  d_in[1];   // adj (32,512,512)
    const float* qv   = (const float*)d_in[2];   // query_vec (32,128)
    const float* mask = (const float*)d_in[3];   // node_mask (32,512,1)
    const float* Wt   = (const float*)d_in[4];   // W_type (3,128,64)
    const float* at   = (const float*)d_in[5];   // a_type (3,128,1)
    const float* W1   = (const float*)d_in[6];   // qattn_W1 (3,128,128)
    const float* W2   = (const float*)d_in[7];   // qattn_W2 (3,128,128)
    float* out = (float*)d_out;                  // (32,512,64)

    const int OUT_SMEM = 2*(64*272) + 2*(64*144) + 384*4;  // 54784
    const int HM_SMEM  = 3072 + 256 + 4*17408;             // 72960
    cudaFuncSetAttribute(out_kernel, cudaFuncAttributeMaxDynamicSharedMemorySize,
                         OUT_SMEM);
    cudaFuncSetAttribute(hm_ssd_kernel, cudaFuncAttributeMaxDynamicSharedMemorySize,
                         HM_SMEM);

    cudaMemsetAsync(d_out, 0, (size_t)out_size * sizeof(float));
    prep_kernel<<<NT*NB, 128>>>(qv, Wt, at, W1, W2);
    hm_ssd_kernel<<<dim3(NB, 8), 256, HM_SMEM>>>(x, Wt, mask);
    rowstats_kernel<<<NB*E/32, 512>>>(adj);
    out_kernel<<<dim3(NB, E/128, 4), 256, OUT_SMEM>>>(out);
}

// round 17
// speedup vs baseline: 1.0721x; 1.0721x over previous
#include <cuda_runtime.h>
#include <cuda_bf16.h>
#include <cstdint>

#define NB 32
#define E  512
#define IND 128
#define OUTD 64
#define NT 3
#define QD 128
#define CD 128   // 2*OUTD

// ---------------- scratch (__device__ globals: no allocs allowed) ----------
__device__ float g_wsrc[NT*NB*IND];
__device__ float g_wdst[NT*NB*IND];
__device__ float g_ssrc[NT*NB*E];
__device__ float g_sdst[NT*NB*E];
__device__ float g_rinvZ[NB*E];
// H transposed, bf16 hi/lo split: [n][d][e]
__device__ __nv_bfloat16 g_hmT_hi[(size_t)NB*OUTD*E];
__device__ __nv_bfloat16 g_hmT_lo[(size_t)NB*OUTD*E];
__device__ unsigned char g_adj8[(size_t)NB*E*E];    // packed adj (values 0..3)

__device__ __forceinline__ uint32_t smem_u32(const void* p) {
    uint32_t a;
    asm("{ .reg .u64 t; cvta.to.shared.u64 t, %1; cvt.u32.u64 %0, t; }"
        : "=r"(a) : "l"(p));
    return a;
}

#define LDSM4_T(R, addr) \
    asm volatile("ldmatrix.sync.aligned.m8n8.x4.trans.shared.b16 {%0,%1,%2,%3}, [%4];" \
        : "=r"((R)[0]), "=r"((R)[1]), "=r"((R)[2]), "=r"((R)[3]) : "r"(addr))
#define LDSM4(R, addr) \
    asm volatile("ldmatrix.sync.aligned.m8n8.x4.shared.b16 {%0,%1,%2,%3}, [%4];" \
        : "=r"((R)[0]), "=r"((R)[1]), "=r"((R)[2]), "=r"((R)[3]) : "r"(addr))
#define MMA16816(d, a, b0v, b1v) \
    asm volatile("mma.sync.aligned.m16n8k16.row.col.f32.bf16.bf16.f32 " \
        "{%0,%1,%2,%3}, {%4,%5,%6,%7}, {%8,%9}, {%0,%1,%2,%3};" \
        : "+f"((d)[0]), "+f"((d)[1]), "+f"((d)[2]), "+f"((d)[3]) \
        : "r"((a)[0]), "r"((a)[1]), "r"((a)[2]), "r"((a)[3]), "r"(b0v), "r"(b1v))

// ---------------------------------------------------------------------------
// Kernel 1: per (t,n) fold qg*a into 128-vectors w_src/w_dst.
// ALSO zeroes the output tensor (grid-stride) — removes the memset launch.
// ---------------------------------------------------------------------------
__global__ void prep_kernel(const float* __restrict__ qv,
                            const float* __restrict__ Wt,
                            const float* __restrict__ at,
                            const float* __restrict__ W1,
                            const float* __restrict__ W2,
                            float* __restrict__ out) {
    // zero out: 1M floats / (96 blocks * 128 thr) via float4
    {
        const float4 z = make_float4(0.f, 0.f, 0.f, 0.f);
        float4* o4 = (float4*)out;
        int total = NB*E*OUTD/4;                   // 262144
        for (int k = blockIdx.x*blockDim.x + threadIdx.x; k < total;
             k += gridDim.x*blockDim.x)
            o4[k] = z;
    }

    int t = blockIdx.x / NB, n = blockIdx.x % NB;
    int c = threadIdx.x;                       // 0..127
    __shared__ float sq[QD], sg1[CD], su[CD];

    sq[c] = qv[n*QD + c];
    __syncthreads();

    const float* w1 = W1 + t*QD*CD;
    float acc = 0.f;
    #pragma unroll 8
    for (int q = 0; q < QD; q++) acc += sq[q] * w1[q*CD + c];
    sg1[c] = fmaxf(acc, 0.f);
    __syncthreads();

    const float* w2 = W2 + t*CD*CD;
    acc = 0.f;
    #pragma unroll 8
    for (int q = 0; q < CD; q++) acc += sg1[q] * w2[q*CD + c];
    float qg = 1.f / (1.f + expf(-acc));
    su[c] = qg * at[t*CD + c];
    __syncthreads();

    const float* W = Wt + (t*IND + c)*OUTD;
    float ws = 0.f, wd = 0.f;
    #pragma unroll 8
    for (int o = 0; o < OUTD; o++) {
        float w = W[o];
        ws += w * su[o];
        wd += w * su[OUTD + o];
    }
    g_wsrc[(t*NB + n)*IND + c] = ws;
    g_wdst[(t*NB + n)*IND + c] = wd;
}

// ---------------------------------------------------------------------------
// Kernel 2 (fused, TENSORIZED): h = (x @ W_type[2]) * mask via bf16 hi/lo
// 3-product mma.sync -> transposed bf16 hi/lo planes; ssd dots folded into
// the x->bf16 conversion pass. grid (NB, 8), 256 threads. (round-15 exact)
// ---------------------------------------------------------------------------
__global__ void __launch_bounds__(256)
hm_ssd_kernel(const float* __restrict__ x, const float* __restrict__ Wt,
              const float* __restrict__ mask) {
    extern __shared__ char sm2[];
    float* sw    = (float*)sm2;                // [6][128]
    float* smask = (float*)(sm2 + 3072);       // [64]
    char*  Xh    = sm2 + 3328;
    char*  Xl    = Xh + 17408;
    char*  Wh    = Xl + 17408;
    char*  Wl    = Wh + 17408;
    float* Hs    = (float*)Xh;                 // alias (post-MMA), pitch 65

    const int n = blockIdx.x, e0 = blockIdx.y * 64;
    const int tid = threadIdx.x;
    const int w = tid >> 5, lane = tid & 31;
    const int wm = w & 3, wn = w >> 2;         // warp tile: e=wm*16, d=wn*32
    const uint32_t sb = smem_u32(sm2);

    for (int k = tid; k < 6*IND; k += 256) {
        int v = k / IND, i = k % IND;
        int t = v % 3;
        sw[k] = (v < 3) ? g_wsrc[(t*NB+n)*IND + i] : g_wdst[(t*NB+n)*IND + i];
    }
    if (tid < 64) smask[tid] = mask[n*E + e0 + tid];

    // W_type[2] transpose + bf16 hi/lo convert: [k][d] -> Wh/Wl[d][k]
    for (int idx = tid; idx < IND*OUTD; idx += 256) {
        int k = idx >> 6, d = idx & 63;
        float v = Wt[2*IND*OUTD + k*OUTD + d];
        __nv_bfloat16 h = __float2bfloat16(v);
        *(__nv_bfloat16*)(Wh + d*272 + k*2) = h;
        *(__nv_bfloat16*)(Wl + d*272 + k*2) = __float2bfloat16(v - __bfloat162float(h));
    }

    // x convert (fp32 -> bf16 hi/lo planes) + ssd accumulate
    {
        int r = tid >> 2, q = tid & 3;         // 4 threads per e-row
        const float* xr = x + ((size_t)n*E + e0 + r)*IND;
        float a[6] = {0.f,0.f,0.f,0.f,0.f,0.f};
        #pragma unroll
        for (int u = 0; u < 8; u++) {
            int k = u*16 + q*4;
            float4 v = *(const float4*)(xr + k);
            #pragma unroll
            for (int j = 0; j < 6; j++) {
                const float* s = &sw[j*IND + k];
                a[j] += v.x*s[0] + v.y*s[1] + v.z*s[2] + v.w*s[3];
            }
            __nv_bfloat16 h0 = __float2bfloat16(v.x), h1 = __float2bfloat16(v.y);
            __nv_bfloat16 h2 = __float2bfloat16(v.z), h3 = __float2bfloat16(v.w);
            __nv_bfloat162 hp0 = __halves2bfloat162(h0, h1);
            __nv_bfloat162 hp1 = __halves2bfloat162(h2, h3);
            *(uint32_t*)(Xh + r*272 + k*2)     = *(uint32_t*)&hp0;
            *(uint32_t*)(Xh + r*272 + k*2 + 4) = *(uint32_t*)&hp1;
            __nv_bfloat162 lp0 = __halves2bfloat162(
                __float2bfloat16(v.x - __bfloat162float(h0)),
                __float2bfloat16(v.y - __bfloat162float(h1)));
            __nv_bfloat162 lp1 = __halves2bfloat162(
                __float2bfloat16(v.z - __bfloat162float(h2)),
                __float2bfloat16(v.w - __bfloat162float(h3)));
            *(uint32_t*)(Xl + r*272 + k*2)     = *(uint32_t*)&lp0;
            *(uint32_t*)(Xl + r*272 + k*2 + 4) = *(uint32_t*)&lp1;
        }
        #pragma unroll
        for (int off = 1; off <= 2; off <<= 1)
            #pragma unroll
            for (int u2 = 0; u2 < 6; u2++)
                a[u2] += __shfl_xor_sync(0xffffffffu, a[u2], off);
        if (q == 0) {
            int e = e0 + r;
            #pragma unroll
            for (int t = 0; t < 3; t++) {
                g_ssrc[(t*NB+n)*E + e] = a[t];
                g_sdst[(t*NB+n)*E + e] = a[t+3];
            }
        }
    }
    __syncthreads();

    // tensor-core h GEMM: A = x[e][k] (non-trans), B = W^T[d][k]
    float acc[2][2][4] = {};                   // [cp][n8][frag]
    const uint32_t aX = sb + 3328
        + (wm*16 + (lane & 7) + ((lane>>3)&1)*8)*272 + ((lane>>4)&1)*16;
    const uint32_t aW = sb + 3328 + 2*17408
        + ((uint32_t)wn*32 + ((lane>>4)&1)*8 + (lane & 7))*272 + ((lane>>3)&1)*16;
    #pragma unroll
    for (int kk = 0; kk < 8; kk++) {
        uint32_t a_h[4], a_l[4];
        LDSM4(a_h, aX + kk*32);
        LDSM4(a_l, aX + 17408 + kk*32);
        #pragma unroll
        for (int cp = 0; cp < 2; cp++) {
            uint32_t b_h[4], b_l[4];
            uint32_t bd = aW + cp*16*272 + kk*32;
            LDSM4(b_h, bd);
            LDSM4(b_l, bd + 17408);
            float* d0 = acc[cp][0];
            float* d1 = acc[cp][1];
            MMA16816(d0, a_h, b_h[0], b_h[1]);
            MMA16816(d0, a_h, b_l[0], b_l[1]);
            MMA16816(d0, a_l, b_h[0], b_h[1]);
            MMA16816(d1, a_h, b_h[2], b_h[3]);
            MMA16816(d1, a_h, b_l[2], b_l[3]);
            MMA16816(d1, a_l, b_h[2], b_h[3]);
        }
    }
    __syncthreads();                           // all X-plane reads done

    // write Hs[e][d] (fp32, mask applied); Hs aliases Xh
    {
        const int g = lane >> 2, t2 = (lane & 3)*2;
        #pragma unroll
        for (int cp = 0; cp < 2; cp++) {
            #pragma unroll
            for (int ct = 0; ct < 2; ct++) {
                int e1 = wm*16 + g;
                int d  = wn*32 + cp*16 + ct*8 + t2;
                float mk0 = smask[e1], mk1 = smask[e1 + 8];
                Hs[e1*65 + d]       = acc[cp][ct][0] * mk0;
                Hs[e1*65 + d + 1]   = acc[cp][ct][1] * mk0;
                Hs[(e1+8)*65 + d]     = acc[cp][ct][2] * mk1;
                Hs[(e1+8)*65 + d + 1] = acc[cp][ct][3] * mk1;
            }
        }
    }
    __syncthreads();

    // coalesced 16B writes of both planes: task = (d, e-group of 8)
    #pragma unroll
    for (int u = 0; u < 2; u++) {
        int task = tid + u*256;                // 0..511
        int d = task >> 3, g = task & 7;
        uint32_t hv[4], lv[4];
        #pragma unroll
        for (int p = 0; p < 4; p++) {
            float v0 = Hs[(g*8 + 2*p + 0)*65 + d];
            float v1 = Hs[(g*8 + 2*p + 1)*65 + d];
            __nv_bfloat16 h0 = __float2bfloat16(v0);
            __nv_bfloat16 h1 = __float2bfloat16(v1);
            __nv_bfloat162 hp = __halves2bfloat162(h0, h1);
            hv[p] = *(uint32_t*)&hp;
            __nv_bfloat162 lp = __halves2bfloat162(
                __float2bfloat16(v0 - __bfloat162float(h0)),
                __float2bfloat16(v1 - __bfloat162float(h1)));
            lv[p] = *(uint32_t*)&lp;
        }
        size_t base = ((size_t)(n*OUTD + d))*E + e0 + g*8;
        *(uint4*)(g_hmT_hi + base) = make_uint4(hv[0], hv[1], hv[2], hv[3]);
        *(uint4*)(g_hmT_lo + base) = make_uint4(lv[0], lv[1], lv[2], lv[3]);
    }
}

// ---------------------------------------------------------------------------
// Kernel 3: row softmax WITHOUT max-subtraction. 2 rows per warp -> ONE wave.
// grid NB*E/32 = 512, block 512. (round-15 exact)
// ---------------------------------------------------------------------------
__global__ void rowstats_kernel(const int* __restrict__ adj) {
    int base = blockIdx.x * 32;                // 32 rows per block, same n
    int n = base / E;
    __shared__ float sds[3][E];
    int tid = threadIdx.x;
    #pragma unroll
    for (int k = tid; k < 3*E; k += 512)
        sds[k >> 9][k & 511] = g_sdst[((k >> 9)*NB + n)*E + (k & 511)];
    __syncthreads();

    int warp = tid >> 5, lane = tid & 31;
    int row0 = base + warp*2, row1 = row0 + 1;
    int i0 = row0 & (E-1), i1 = row1 & (E-1);
    float sA0 = g_ssrc[(0*NB+n)*E + i0];
    float sA1 = g_ssrc[(1*NB+n)*E + i0];
    float sA2 = g_ssrc[(2*NB+n)*E + i0];
    float sB0 = g_ssrc[(0*NB+n)*E + i1];
    float sB1 = g_ssrc[(1*NB+n)*E + i1];
    float sB2 = g_ssrc[(2*NB+n)*E + i1];
    const int* ar0 = adj + (size_t)row0 * E;
    const int* ar1 = adj + (size_t)row1 * E;
    unsigned char* a80 = g_adj8 + (size_t)row0 * E;
    unsigned char* a81 = g_adj8 + (size_t)row1 * E;

    float sum0 = 0.f, sum1 = 0.f;
    #pragma unroll
    for (int k = 0; k < 16; k++) {
        int j = lane + 32*k;
        int v0 = ar0[j];
        int v1 = ar1[j];
        a80[j] = (unsigned char)v0;
        a81[j] = (unsigned char)v1;
        float s0 = -1e30f, s1 = -1e30f;
        if (v0 > 0) {
            float srr = (v0 == 1) ? sA0 : ((v0 == 2) ? sA1 : sA2);
            float t2 = srr + sds[v0-1][j];
            s0 = (t2 >= 0.f) ? t2 : 0.2f*t2;
        }
        if (v1 > 0) {
            float srr = (v1 == 1) ? sB0 : ((v1 == 2) ? sB1 : sB2);
            float t2 = srr + sds[v1-1][j];
            s1 = (t2 >= 0.f) ? t2 : 0.2f*t2;
        }
        sum0 += __expf(s0);
        sum1 += __expf(s1);
    }
    #pragma unroll
    for (int off = 16; off > 0; off >>= 1) {
        sum0 += __shfl_xor_sync(~0u, sum0, off);
        sum1 += __shfl_xor_sync(~0u, sum1, off);
    }
    if (lane == 0) {
        g_rinvZ[row0] = 1.f / sum0;
        g_rinvZ[row1] = 1.f / sum1;
    }
}

// ---------------------------------------------------------------------------
// Kernel 4: output GEMM on tensor cores (round-16 structure: register stats,
// 2 barriers/chunk). CHANGE: float2 RED.ADD epilogue (16 atomics vs 32).
// grid (NB, E/128, 4), 256 thr, occ 4.
// ---------------------------------------------------------------------------
__global__ void __launch_bounds__(256, 4)
out_kernel(float* __restrict__ out) {
    extern __shared__ char sm[];
    const int CPL = 64*272;
    const int HPL = 64*144;
    char* Chi = sm;
    char* Hhi = sm + 2*CPL;
    char* Hlo = sm + 2*CPL + HPL;
    float* sds = (float*)(sm + 2*CPL + 2*HPL);  // [3][128]

    const int n = blockIdx.x, j0t = blockIdx.y * 128, kz = blockIdx.z;
    const int tid = threadIdx.x;
    const int w = tid >> 5, lane = tid & 31;
    const int wm = w & 3, wn = w >> 2;

    const uint32_t sbase = smem_u32(sm);

    for (int k = tid; k < 384; k += 256)
        sds[k] = g_sdst[((k>>7)*NB + n)*E + j0t + (k & 127)];

    float acc[2][4][4] = {};

    const uint32_t lr = lane & 7;
    const uint32_t aA0 = sbase
        + (((lane>>4)&1)*8 + lr)*272
        + (wm*32 + ((lane>>3)&1)*8)*2;
    const uint32_t aB0 = sbase + 2*CPL
        + ((uint32_t)wn*32 + ((lane>>4)&1)*8 + lr)*144
        + ((lane>>3)&1)*16;

    for (int ch = 0; ch < 2; ch++) {
        const int ic = kz*128 + ch*64;
        __syncthreads();                         // prev chunk's mma reads done
                                                 // (also covers sds on ch==0)

        // per-warp stats in registers: lane = (vv<<3)|s holds stat vv of
        // i-row (s*8 + w); vv: 0..2 = ssr[t], 3 = invZ
        float statv;
        {
            int s = lane & 7, vv = lane >> 3;
            int irow = ic + s*8 + w;
            statv = (vv < 3) ? g_ssrc[(vv*NB + n)*E + irow]
                             : g_rinvZ[n*E + irow];
        }

        // stage H^T hi/lo tiles (overlaps with gen below — same barrier)
        #pragma unroll
        for (int u = 0; u < 2; u++) {
            int k = tid + u*256;
            int d = k >> 3, i16 = k & 7;
            size_t src = ((size_t)(n*OUTD + d))*E + ic + i16*8;
            *(uint4*)(Hhi + d*144 + i16*16) = *(const uint4*)(g_hmT_hi + src);
            *(uint4*)(Hlo + d*144 + i16*16) = *(const uint4*)(g_hmT_lo + src);
        }

        // generate coef tile: warp w handles i rows {8s + w}
        const unsigned char* abase = g_adj8 + ((size_t)(n*E + ic))*E + j0t;
        #pragma unroll
        for (int s = 0; s < 8; s++) {
            int i = s*8 + w;
            uint32_t a4 = *(const uint32_t*)(abase + (size_t)i*E + lane*4);
            float s0 = __shfl_sync(~0u, statv, s);
            float s1 = __shfl_sync(~0u, statv, 8 + s);
            float s2 = __shfl_sync(~0u, statv, 16 + s);
            float z  = __shfl_sync(~0u, statv, 24 + s);
            float cf[4];
            #pragma unroll
            for (int q = 0; q < 4; q++) {
                int v = (int)((a4 >> (8*q)) & 0xFFu);
                float score = -1e30f;
                if (v > 0) {
                    float srr = (v == 1) ? s0 : ((v == 2) ? s1 : s2);
                    float t2 = srr + sds[(v-1)*128 + lane*4 + q];
                    score = (t2 >= 0.f) ? t2 : 0.2f*t2;
                }
                cf[q] = __expf(score) * z;
            }
            __nv_bfloat16 h0 = __float2bfloat16(cf[0]), h1 = __float2bfloat16(cf[1]);
            __nv_bfloat16 h2 = __float2bfloat16(cf[2]), h3 = __float2bfloat16(cf[3]);
            uint2 hv;
            ((__nv_bfloat162*)&hv)[0] = __halves2bfloat162(h0, h1);
            ((__nv_bfloat162*)&hv)[1] = __halves2bfloat162(h2, h3);
            uint2 lv;
            ((__nv_bfloat162*)&lv)[0] = __halves2bfloat162(
                __float2bfloat16(cf[0] - __bfloat162float(h0)),
                __float2bfloat16(cf[1] - __bfloat162float(h1)));
            ((__nv_bfloat162*)&lv)[1] = __halves2bfloat162(
                __float2bfloat16(cf[2] - __bfloat162float(h2)),
                __float2bfloat16(cf[3] - __bfloat162float(h3)));
            *(uint2*)(Chi + i*272 + lane*8)       = hv;
            *(uint2*)(Chi + CPL + i*272 + lane*8) = lv;
        }
        __syncthreads();                         // C + H visible to mma

        #pragma unroll
        for (int kk = 0; kk < 4; kk++) {
            uint32_t a_h[2][4], a_l[2][4];
            #pragma unroll
            for (int r = 0; r < 2; r++) {
                uint32_t ad = aA0 + kk*16*272 + r*32;
                LDSM4_T(a_h[r], ad);
                LDSM4_T(a_l[r], ad + CPL);
            }
            #pragma unroll
            for (int cp = 0; cp < 2; cp++) {
                uint32_t b_h[4], b_l[4];
                uint32_t bd = aB0 + cp*16*144 + kk*32;
                LDSM4(b_h, bd);
                LDSM4(b_l, bd + HPL);
                #pragma unroll
                for (int r = 0; r < 2; r++) {
                    float* d0 = acc[r][cp*2 + 0];
                    float* d1 = acc[r][cp*2 + 1];
                    MMA16816(d0, a_h[r], b_h[0], b_h[1]);
                    MMA16816(d0, a_h[r], b_l[0], b_l[1]);
                    MMA16816(d0, a_l[r], b_h[0], b_h[1]);
                    MMA16816(d1, a_h[r], b_h[2], b_h[3]);
                    MMA16816(d1, a_h[r], b_l[2], b_l[3]);
                    MMA16816(d1, a_l[r], b_h[2], b_h[3]);
                }
            }
        }
    }

    // epilogue: float2 RED.ADD (half the atomic ops) onto zeroed out
    const int g = lane >> 2, t2 = (lane & 3)*2;
    #pragma unroll
    for (int r = 0; r < 2; r++) {
        #pragma unroll
        for (int ct = 0; ct < 4; ct++) {
            int j = j0t + wm*32 + r*16 + g;
            int d = wn*32 + ct*8 + t2;
            float* p = out + ((size_t)(n*E + j))*OUTD + d;
            atomicAdd((float2*)p, make_float2(acc[r][ct][0], acc[r][ct][1]));
            atomicAdd((float2*)(p + 8*OUTD), make_float2(acc[r][ct][2], acc[r][ct][3]));
        }
    }
}

// ---------------------------------------------------------------------------
extern "C" void kernel_launch(void* const* d_in, const int* in_sizes, int n_in,
                              void* d_out, int out_size) {
    const float* x    = (const float*)d_in[0];   // input_state (32,512,128)
    const int*   adj  = (const int*)  d_in[1];   // adj (32,512,512)
    const float* qv   = (const float*)d_in[2];   // query_vec (32,128)
    const float* mask = (const float*)d_in[3];   // node_mask (32,512,1)
    const float* Wt   = (const float*)d_in[4];   // W_type (3,128,64)
    const float* at   = (const float*)d_in[5];   // a_type (3,128,1)
    const float* W1   = (const float*)d_in[6];   // qattn_W1 (3,128,128)
    const float* W2   = (const float*)d_in[7];   // qattn_W2 (3,128,128)
    float* out = (float*)d_out;                  // (32,512,64)

    const int OUT_SMEM = 2*(64*272) + 2*(64*144) + 384*4;  // 54784
    const int HM_SMEM  = 3072 + 256 + 4*17408;             // 72960
    cudaFuncSetAttribute(out_kernel, cudaFuncAttributeMaxDynamicSharedMemorySize,
                         OUT_SMEM);
    cudaFuncSetAttribute(hm_ssd_kernel, cudaFuncAttributeMaxDynamicSharedMemorySize,
                         HM_SMEM);

    prep_kernel<<<NT*NB, 128>>>(qv, Wt, at, W1, W2, out);
    hm_ssd_kernel<<<dim3(NB, 8), 256, HM_SMEM>>>(x, Wt, mask);
    rowstats_kernel<<<NB*E/32, 512>>>(adj);
    out_kernel<<<dim3(NB, E/128, 4), 256, OUT_SMEM>>>(out);
}